// round 8
// baseline (speedup 1.0000x reference)
#include <cuda_runtime.h>

#define NN 100000
#define EE 1600000
#define CAP 64   // max in-degree bucket capacity (Poisson(16): P(exceed) ~ 1e-19)
#define FULLM 0xffffffffu
#define S 4      // threads per node
#define LS 2     // log2(S)

// ---------------- scratch ---------------------------------------------------
__device__ int    g_cnt[NN];           // in-degree
__device__ int    g_slot[CAP * NN];    // src ids: slot[j*NN + dst], j < cnt[dst]
__device__ float4 g_bufA4[NN * 4];     // ping (max padded C = 16)
__device__ float4 g_bufB4[NN * 4];     // pong
__device__ float  g_stats[192];        // 3 layers x (32 sum + 32 sumsq)

// ---------------- bucket fill: one pass, column-major slots ------------------
__global__ void k_fill(const int* __restrict__ ei) {
    int e = blockIdx.x * blockDim.x + threadIdx.x;
    if (e >= EE) return;
    int s = ei[e];
    int d = ei[EE + e];
    int pos = atomicAdd(&g_cnt[d], 1);
    if (pos < CAP) g_slot[pos * NN + d] = s;
}

// ---------------- fused layer (S threads per node) ---------------------------
// gather-mean + (BN folded into weights) + lin_l + lin_r + L2norm + relu
// (+ BN partial sums for the NEXT layer unless LAST)
template <int CI, int CO, int CPI, int CPO, bool LAST, bool HAS_BN,
          int SIN, int SOUT>
__global__ void node_kernel(const float4* __restrict__ x4,
                            const float* __restrict__ wl,
                            const float* __restrict__ bl,
                            const float* __restrict__ wr,
                            const float* __restrict__ bn_g,
                            const float* __restrict__ bn_b,
                            float* __restrict__ y) {
    constexpr int V   = CPI / 4;            // float4 chunks per input row
    constexpr int NCC = (CO + S - 1) / S;   // channels per lane
    constexpr int NPC = (CPO + S - 1) / S;  // padded channels per lane
    __shared__ float s_wl[CO * CI];
    __shared__ float s_wr[CO * CI];
    __shared__ float s_bias[CO];
    __shared__ float s_sc[CI], s_sh[CI];
    __shared__ float s_sum[CO];
    __shared__ float s_sq[CO];

    if (HAS_BN) {
        if (threadIdx.x < CI) {
            int c = threadIdx.x;
            float m  = g_stats[SIN + c] * (1.0f / NN);
            float v  = g_stats[SIN + 32 + c] * (1.0f / NN) - m * m;
            float sc = bn_g[c] * rsqrtf(v + 1e-5f);
            s_sc[c] = sc;
            s_sh[c] = bn_b[c] - m * sc;
        }
        __syncthreads();
    }
    for (int i = threadIdx.x; i < CO * CI; i += blockDim.x) {
        float sc = HAS_BN ? s_sc[i % CI] : 1.0f;
        s_wl[i] = wl[i] * sc;
        s_wr[i] = wr[i] * sc;
    }
    if (threadIdx.x < CO) {
        int co = threadIdx.x;
        float b = bl[co];
        if (HAS_BN) {
#pragma unroll
            for (int i = 0; i < CI; i++)
                b += s_sh[i] * (wl[co * CI + i] + wr[co * CI + i]);
        }
        s_bias[co] = b;
        if (!LAST) { s_sum[co] = 0.0f; s_sq[co] = 0.0f; }
    }
    __syncthreads();

    int t = blockIdx.x * blockDim.x + threadIdx.x;
    int n = t >> LS;                 // node
    int p = t & (S - 1);             // part within node
    bool act = (n < NN);

    // ---- gather: this lane handles edges j = p, p+S, p+2S, ... --------------
    float4 acc[V];
#pragma unroll
    for (int v = 0; v < V; v++) acc[v] = make_float4(0.f, 0.f, 0.f, 0.f);

    int deg = act ? min(g_cnt[n], CAP) : 0;
    for (int j = p; j < deg; j += S) {
        int s0 = g_slot[j * NN + n];
        const float4* r0 = x4 + (size_t)s0 * V;
#pragma unroll
        for (int v = 0; v < V; v++) {
            float4 a0 = r0[v];
            acc[v].x += a0.x; acc[v].y += a0.y;
            acc[v].z += a0.z; acc[v].w += a0.w;
        }
    }

    // ---- merge partial sums across the S-lane group -------------------------
#pragma unroll
    for (int off = 1; off < S; off <<= 1) {
#pragma unroll
        for (int v = 0; v < V; v++) {
            acc[v].x += __shfl_xor_sync(FULLM, acc[v].x, off);
            acc[v].y += __shfl_xor_sync(FULLM, acc[v].y, off);
            acc[v].z += __shfl_xor_sync(FULLM, acc[v].z, off);
            acc[v].w += __shfl_xor_sync(FULLM, acc[v].w, off);
        }
    }

    // ---- self row (redundant load, L1 broadcast within group) ---------------
    float4 xv4[V];
#pragma unroll
    for (int v = 0; v < V; v++)
        xv4[v] = act ? x4[(size_t)n * V + v] : make_float4(0.f, 0.f, 0.f, 0.f);

    float cinv = 1.0f / (float)max(deg, 1);
    float av[CI], xv[CI];
    {
        const float* ap = reinterpret_cast<const float*>(acc);
        const float* xp = reinterpret_cast<const float*>(xv4);
#pragma unroll
        for (int i = 0; i < CI; i++) { av[i] = ap[i] * cinv; xv[i] = xp[i]; }
    }

    // ---- epilogue split: lane p computes channels c = p + cc*S --------------
    float outl[NCC];
    float ss = 0.0f;
#pragma unroll
    for (int cc = 0; cc < NCC; cc++) {
        int c = p + cc * S;
        float tacc = 0.0f;
        if (c < CO) {
            tacc = s_bias[c];
#pragma unroll
            for (int i = 0; i < CI; i++) {
                tacc = fmaf(av[i], s_wl[c * CI + i], tacc);
                tacc = fmaf(xv[i], s_wr[c * CI + i], tacc);
            }
        }
        outl[cc] = tacc;
        ss += tacc * tacc;
    }
#pragma unroll
    for (int off = 1; off < S; off <<= 1)
        ss += __shfl_xor_sync(FULLM, ss, off);
    float inv = 1.0f / fmaxf(sqrtf(ss), 1e-12f);

    float lsum[NCC], lsq[NCC];
#pragma unroll
    for (int cc = 0; cc < NCC; cc++) {
        float o = fmaxf(outl[cc] * inv, 0.0f);     // L2 norm then relu
        o = act ? o : 0.0f;
        outl[cc] = o;
        lsum[cc] = o;
        lsq[cc]  = o * o;
    }

    // ---- store (lane p writes channels c = p+cc*S; pads zeroed) -------------
    if (act) {
#pragma unroll
        for (int cc = 0; cc < NPC; cc++) {
            int c = p + cc * S;
            if (c < CPO) y[(size_t)n * CPO + c] = (cc < NCC) ? outl[cc] : 0.0f;
        }
    }

    if (!LAST) {
        // reduce stats across the 8 node-groups in this warp (node bits only)
#pragma unroll
        for (int off = S; off < 32; off <<= 1) {
#pragma unroll
            for (int cc = 0; cc < NCC; cc++) {
                lsum[cc] += __shfl_xor_sync(FULLM, lsum[cc], off);
                lsq[cc]  += __shfl_xor_sync(FULLM, lsq[cc],  off);
            }
        }
        if ((threadIdx.x & 31) < S) {
#pragma unroll
            for (int cc = 0; cc < NCC; cc++) {
                int c = p + cc * S;
                if (c < CO) {
                    atomicAdd(&s_sum[c], lsum[cc]);
                    atomicAdd(&s_sq[c],  lsq[cc]);
                }
            }
        }
        __syncthreads();
        if (threadIdx.x < CO) {
            atomicAdd(&g_stats[SOUT + threadIdx.x], s_sum[threadIdx.x]);
            atomicAdd(&g_stats[SOUT + 32 + threadIdx.x], s_sq[threadIdx.x]);
        }
    }
}

// ---------------- launch ----------------------------------------------------
extern "C" void kernel_launch(void* const* d_in, const int* in_sizes, int n_in,
                              void* d_out, int out_size) {
    const float* x   = (const float*)d_in[0];
    const int*   ei  = (const int*)d_in[1];     // int32 edge_index (JAX x64 off)
    const float* w1l = (const float*)d_in[2];
    const float* b1l = (const float*)d_in[3];
    const float* w1r = (const float*)d_in[4];
    const float* w2l = (const float*)d_in[5];
    const float* b2l = (const float*)d_in[6];
    const float* w2r = (const float*)d_in[7];
    const float* w3l = (const float*)d_in[8];
    const float* b3l = (const float*)d_in[9];
    const float* w3r = (const float*)d_in[10];
    const float* w4l = (const float*)d_in[11];
    const float* b4l = (const float*)d_in[12];
    const float* w4r = (const float*)d_in[13];
    const float* g1  = (const float*)d_in[14];
    const float* be1 = (const float*)d_in[15];
    const float* g2  = (const float*)d_in[16];
    const float* be2 = (const float*)d_in[17];
    const float* g3  = (const float*)d_in[18];
    const float* be3 = (const float*)d_in[19];
    float* out = (float*)d_out;

    void *p_cnt, *p_stats, *p_bufA, *p_bufB;
    cudaGetSymbolAddress(&p_cnt, g_cnt);
    cudaGetSymbolAddress(&p_stats, g_stats);
    cudaGetSymbolAddress(&p_bufA, g_bufA4);
    cudaGetSymbolAddress(&p_bufB, g_bufB4);
    float* bufA = (float*)p_bufA;
    float* bufB = (float*)p_bufB;

    const int TB = 256;
    const int gridE = (EE + TB - 1) / TB;
    const int gridN = ((NN * S) + TB - 1) / TB;   // S threads per node

    // bucket build (single pass)
    cudaMemsetAsync(p_cnt, 0, NN * sizeof(int));
    cudaMemsetAsync(p_stats, 0, 192 * sizeof(float));
    k_fill<<<gridE, TB>>>(ei);

    // L1: 4 -> 6 (pad 8), no input BN
    node_kernel<4, 6, 4, 8, false, false, 0, 0>
        <<<gridN, TB>>>((const float4*)x, w1l, b1l, w1r, nullptr, nullptr, bufA);

    // L2: 6 (pad 8) -> 8, BN1 folded
    node_kernel<6, 8, 8, 8, false, true, 0, 64>
        <<<gridN, TB>>>((const float4*)bufA, w2l, b2l, w2r, g1, be1, bufB);

    // L3: 8 -> 16, BN2 folded
    node_kernel<8, 16, 8, 16, false, true, 64, 128>
        <<<gridN, TB>>>((const float4*)bufB, w3l, b3l, w3r, g2, be2, bufA);

    // L4: 16 -> 32, BN3 folded, final relu straight to d_out
    node_kernel<16, 32, 16, 32, true, true, 128, 0>
        <<<gridN, TB>>>((const float4*)bufA, w4l, b4l, w4r, g3, be3, out);
}

// round 10
// speedup vs baseline: 1.0042x; 1.0042x over previous
#include <cuda_runtime.h>
#include <cuda_fp16.h>

#define NN 100000
#define EE 1600000
#define CAP 64   // max in-degree bucket capacity (Poisson(16): P(exceed) ~ 1e-19)

// ---------------- scratch ---------------------------------------------------
__device__ int    g_cnt[NN];           // in-degree
__device__ int    g_slot[CAP * NN];    // src ids: slot[j*NN + dst], j < cnt[dst]
__device__ uint4  g_bufA4[NN * 2];     // ping: fp16 rows, max 16 ch = 32B = 2 uint4
__device__ uint4  g_bufB4[NN * 2];     // pong
__device__ float  g_stats[192];        // 3 layers x (32 sum + 32 sumsq)

// ---------------- bucket fill: one pass, column-major slots ------------------
__global__ void k_fill(const int* __restrict__ ei) {
    int e = blockIdx.x * blockDim.x + threadIdx.x;
    if (e >= EE) return;
    int s = ei[e];
    int d = ei[EE + e];
    int pos = atomicAdd(&g_cnt[d], 1);
    if (pos < CAP) g_slot[pos * NN + d] = s;
}

// ---------------- chunk decode-add: 16B chunk -> fp32 accumulate -------------
template <bool H>
__device__ __forceinline__ void dec_add(uint4 r, float* acc) {
    if (H) {
        __half2 h[4];
        *reinterpret_cast<uint4*>(h) = r;
#pragma unroll
        for (int k = 0; k < 4; k++) {
            float2 f = __half22float2(h[k]);
            acc[2 * k] += f.x;
            acc[2 * k + 1] += f.y;
        }
    } else {
        float4 f = *reinterpret_cast<float4*>(&r);
        acc[0] += f.x; acc[1] += f.y; acc[2] += f.z; acc[3] += f.w;
    }
}

// ---------------- fused layer ------------------------------------------------
// gather-mean + (BN folded into weights) + lin_l + lin_r + L2norm + relu
// (+ BN partial sums for the NEXT layer unless LAST)
// IN_H / OUT_H: fp16 storage for input/output feature rows (math is fp32).
template <int CI, int CO, int CPI, int CPO, bool LAST, bool HAS_BN,
          bool IN_H, bool OUT_H, int SIN, int SOUT>
__global__ void node_kernel(const uint4* __restrict__ xu,
                            const float* __restrict__ wl,
                            const float* __restrict__ bl,
                            const float* __restrict__ wr,
                            const float* __restrict__ bn_g,
                            const float* __restrict__ bn_b,
                            void* __restrict__ yout) {
    constexpr int FPC = IN_H ? 8 : 4;          // floats per 16B chunk
    constexpr int VI  = CPI / FPC;             // input chunks per row
    constexpr int WO  = OUT_H ? (CPO * 2 / 16) : (CPO * 4 / 16);  // out chunks
    __shared__ float s_wl[CO * CI];
    __shared__ float s_wr[CO * CI];
    __shared__ float s_bias[CO];
    __shared__ float s_sc[CI], s_sh[CI];
    __shared__ float s_sum[CO];
    __shared__ float s_sq[CO];

    if (HAS_BN) {
        if (threadIdx.x < CI) {
            int c = threadIdx.x;
            float m  = g_stats[SIN + c] * (1.0f / NN);
            float v  = g_stats[SIN + 32 + c] * (1.0f / NN) - m * m;
            float sc = bn_g[c] * rsqrtf(v + 1e-5f);
            s_sc[c] = sc;
            s_sh[c] = bn_b[c] - m * sc;
        }
        __syncthreads();
    }
    for (int i = threadIdx.x; i < CO * CI; i += blockDim.x) {
        float sc = HAS_BN ? s_sc[i % CI] : 1.0f;
        s_wl[i] = wl[i] * sc;
        s_wr[i] = wr[i] * sc;
    }
    if (threadIdx.x < CO) {
        int co = threadIdx.x;
        float b = bl[co];
        if (HAS_BN) {
#pragma unroll
            for (int i = 0; i < CI; i++)
                b += s_sh[i] * (wl[co * CI + i] + wr[co * CI + i]);
        }
        s_bias[co] = b;
        if (!LAST) { s_sum[co] = 0.0f; s_sq[co] = 0.0f; }
    }
    __syncthreads();

    int n = blockIdx.x * blockDim.x + threadIdx.x;
    bool act = (n < NN);

    float out[CO];
#pragma unroll
    for (int c = 0; c < CO; c++) out[c] = 0.0f;

    if (act) {
        // self row
        float xv[CPI];
#pragma unroll
        for (int i = 0; i < CPI; i++) xv[i] = 0.0f;
        {
            uint4 raw[VI];
#pragma unroll
            for (int v = 0; v < VI; v++) raw[v] = xu[(size_t)n * VI + v];
#pragma unroll
            for (int v = 0; v < VI; v++) dec_add<IN_H>(raw[v], xv + v * FPC);
        }

        // gather-mean (2-edge batched loads, fp32 accumulate)
        float acc[CPI];
#pragma unroll
        for (int i = 0; i < CPI; i++) acc[i] = 0.0f;

        int deg = min(g_cnt[n], CAP);
        int j = 0;
        for (; j + 1 < deg; j += 2) {
            int s0 = g_slot[j * NN + n];
            int s1 = g_slot[(j + 1) * NN + n];
            uint4 a0[VI], a1[VI];
#pragma unroll
            for (int v = 0; v < VI; v++) a0[v] = xu[(size_t)s0 * VI + v];
#pragma unroll
            for (int v = 0; v < VI; v++) a1[v] = xu[(size_t)s1 * VI + v];
#pragma unroll
            for (int v = 0; v < VI; v++) {
                dec_add<IN_H>(a0[v], acc + v * FPC);
                dec_add<IN_H>(a1[v], acc + v * FPC);
            }
        }
        if (j < deg) {
            int s0 = g_slot[j * NN + n];
            uint4 a0[VI];
#pragma unroll
            for (int v = 0; v < VI; v++) a0[v] = xu[(size_t)s0 * VI + v];
#pragma unroll
            for (int v = 0; v < VI; v++) dec_add<IN_H>(a0[v], acc + v * FPC);
        }

        float cinv = 1.0f / (float)max(deg, 1);
        float ss = 0.0f;
#pragma unroll
        for (int co = 0; co < CO; co++) {
            float t = s_bias[co];
#pragma unroll
            for (int i = 0; i < CI; i++) {
                t = fmaf(acc[i] * cinv, s_wl[co * CI + i], t);
                t = fmaf(xv[i], s_wr[co * CI + i], t);
            }
            out[co] = t;
            ss += t * t;
        }
        float inv = 1.0f / fmaxf(sqrtf(ss), 1e-12f);
#pragma unroll
        for (int co = 0; co < CO; co++)
            out[co] = fmaxf(out[co] * inv, 0.0f);   // L2 norm then relu

        // store row
        if (OUT_H) {
            uint4 orow[WO];
            __half2* oh = reinterpret_cast<__half2*>(orow);
#pragma unroll
            for (int k = 0; k < CPO / 2; k++) {
                float lo = (2 * k < CO) ? out[2 * k < CO ? 2 * k : 0] : 0.0f;
                float hi = (2 * k + 1 < CO) ? out[2 * k + 1 < CO ? 2 * k + 1 : 0] : 0.0f;
                oh[k] = __floats2half2_rn(lo, hi);
            }
            uint4* yr = reinterpret_cast<uint4*>(yout) + (size_t)n * WO;
#pragma unroll
            for (int w = 0; w < WO; w++) yr[w] = orow[w];
        } else {
            float4* yr = reinterpret_cast<float4*>(yout) + (size_t)n * WO;
#pragma unroll
            for (int w = 0; w < WO; w++) {
                float4 o;
                o.x = out[4 * w + 0];
                o.y = out[4 * w + 1];
                o.z = out[4 * w + 2];
                o.w = out[4 * w + 3];
                yr[w] = o;
            }
        }
    }

    if (!LAST) {
        // BN batch-stat partial sums: warp shfl -> smem -> global
#pragma unroll
        for (int c = 0; c < CO; c++) {
            float v = out[c];
            float q = v * v;
#pragma unroll
            for (int off = 16; off; off >>= 1) {
                v += __shfl_xor_sync(0xffffffffu, v, off);
                q += __shfl_xor_sync(0xffffffffu, q, off);
            }
            if ((threadIdx.x & 31) == 0) {
                atomicAdd(&s_sum[c], v);
                atomicAdd(&s_sq[c], q);
            }
        }
        __syncthreads();
        if (threadIdx.x < CO) {
            atomicAdd(&g_stats[SOUT + threadIdx.x], s_sum[threadIdx.x]);
            atomicAdd(&g_stats[SOUT + 32 + threadIdx.x], s_sq[threadIdx.x]);
        }
    }
}

// ---------------- launch ----------------------------------------------------
extern "C" void kernel_launch(void* const* d_in, const int* in_sizes, int n_in,
                              void* d_out, int out_size) {
    const float* x   = (const float*)d_in[0];
    const int*   ei  = (const int*)d_in[1];     // int32 edge_index (JAX x64 off)
    const float* w1l = (const float*)d_in[2];
    const float* b1l = (const float*)d_in[3];
    const float* w1r = (const float*)d_in[4];
    const float* w2l = (const float*)d_in[5];
    const float* b2l = (const float*)d_in[6];
    const float* w2r = (const float*)d_in[7];
    const float* w3l = (const float*)d_in[8];
    const float* b3l = (const float*)d_in[9];
    const float* w3r = (const float*)d_in[10];
    const float* w4l = (const float*)d_in[11];
    const float* b4l = (const float*)d_in[12];
    const float* w4r = (const float*)d_in[13];
    const float* g1  = (const float*)d_in[14];
    const float* be1 = (const float*)d_in[15];
    const float* g2  = (const float*)d_in[16];
    const float* be2 = (const float*)d_in[17];
    const float* g3  = (const float*)d_in[18];
    const float* be3 = (const float*)d_in[19];

    void *p_cnt, *p_stats, *p_bufA, *p_bufB;
    cudaGetSymbolAddress(&p_cnt, g_cnt);
    cudaGetSymbolAddress(&p_stats, g_stats);
    cudaGetSymbolAddress(&p_bufA, g_bufA4);
    cudaGetSymbolAddress(&p_bufB, g_bufB4);
    uint4* bufA = (uint4*)p_bufA;
    uint4* bufB = (uint4*)p_bufB;

    const int TB = 256;
    const int gridE = (EE + TB - 1) / TB;
    const int gridN = (NN + TB - 1) / TB;

    // bucket build (single pass)
    cudaMemsetAsync(p_cnt, 0, NN * sizeof(int));
    cudaMemsetAsync(p_stats, 0, 192 * sizeof(float));
    k_fill<<<gridE, TB>>>(ei);

    // L1: 4 -> 6 (pad 8), fp32 in (harness x), fp16 out
    node_kernel<4, 6, 4, 8, false, false, false, true, 0, 0>
        <<<gridN, TB>>>((const uint4*)x, w1l, b1l, w1r, nullptr, nullptr, bufA);

    // L2: 6 (pad 8) -> 8, BN1 folded, fp16 in/out
    node_kernel<6, 8, 8, 8, false, true, true, true, 0, 64>
        <<<gridN, TB>>>(bufA, w2l, b2l, w2r, g1, be1, bufB);

    // L3: 8 -> 16, BN2 folded, fp16 in/out
    node_kernel<8, 16, 8, 16, false, true, true, true, 64, 128>
        <<<gridN, TB>>>(bufB, w3l, b3l, w3r, g2, be2, bufA);

    // L4: 16 -> 32, BN3 folded, fp16 in, fp32 out straight to d_out
    node_kernel<16, 32, 16, 32, true, true, true, false, 128, 0>
        <<<gridN, TB>>>(bufA, w4l, b4l, w4r, g3, be3, d_out);
}